// round 10
// baseline (speedup 1.0000x reference)
#include <cuda_runtime.h>

// Problem constants (fixed by the reference)
constexpr int B  = 8;
constexpr int C  = 256;
constexpr int H  = 64;
constexpr int W  = 64;
constexpr int WC = 16;          // weight channels
constexpr int G  = C / WC;      // 16 groups sharing each weight
constexpr int HW = H * W;       // 4096
constexpr int Q  = HW / 4;      // float4 quads per plane = 1024
constexpr int GSTRIDE = WC * HW; // plane stride between groups (65536 floats)

// One thread = one (b, wc, 2-row pair of quads) over all 16 groups.
//  - 4 x-rows per group feed BOTH output rows; shuffles shared by both.
//  - 18 weight float4s register-resident across all 16 groups.
//  - next group's rows prefetched before computing the current one.
//  - 64-thread CTAs, 8/SM (reg cap 128): grid=1024 in ONE wave (cap 1184).
__global__ __launch_bounds__(64, 8) void agg_kernel_v7(
    const float* __restrict__ x,
    const float* __restrict__ w,
    float* __restrict__ out)
{
    const int idx  = blockIdx.x * 64 + threadIdx.x;  // 0 .. 65535
    const int q2   = idx & 511;            // 32 row-pairs x 16 quad-cols
    const int wc   = (idx >> 9) & (WC - 1);
    const int b    = idx >> 13;
    const int qcol = q2 & 15;
    const int oh   = (q2 >> 4) << 1;       // even output row
    const int p4   = oh * W + qcol * 4;    // first pixel of top quad

    // Edge masks as float multipliers (no live predicates in the hot loop).
    const float mL = (qcol == 0)  ? 0.f : 1.f;
    const float mR = (qcol == 15) ? 0.f : 1.f;
    const bool ym  = (oh > 0);             // x row oh-1 exists
    const bool yp  = (oh < H - 2);         // x row oh+2 exists

    // Weights: 9 taps for output row oh (wv0) and row oh+1 (wv1).
    const float4* wp = (const float4*)(w + ((size_t)(b * WC + wc) * 9) * HW + p4);
    float4 wv0[9], wv1[9];
    #pragma unroll
    for (int t = 0; t < 9; t++) {
        wv0[t] = wp[(size_t)t * Q];
        wv1[t] = wp[(size_t)t * Q + 16];   // +64 floats = next row
    }

    const float* xc   = x   + (size_t)(b * C + wc) * HW + p4;  // group 0 top quad
    float*       op   = out + (size_t)(b * C + wc) * HW + p4;

    const float4 z4 = make_float4(0.f, 0.f, 0.f, 0.f);

    auto load_rows = [&](float4* c, const float* p) {
        c[0] = ym ? *(const float4*)(p - W)     : z4;
        c[1] =      *(const float4*)(p);
        c[2] =      *(const float4*)(p + W);
        c[3] = yp ? *(const float4*)(p + 2 * W) : z4;
    };

    float4 buf0[4], buf1[4];
    load_rows(buf0, xc);

    #pragma unroll
    for (int g = 0; g < G; g++) {
        float4* c = (g & 1) ? buf1 : buf0;
        float4* n = (g & 1) ? buf0 : buf1;

        // Prefetch next group's rows before computing this one.
        xc += GSTRIDE;
        if (g < G - 1) load_rows(n, xc);

        float4 acc0 = z4, acc1 = z4;

        #pragma unroll
        for (int a = 0; a < 4; a++) {
            const float4 cc = c[a];
            float lf = __shfl_up_sync(0xffffffffu, cc.w, 1) * mL;
            float rt = __shfl_down_sync(0xffffffffu, cc.x, 1) * mR;

            if (a < 3) {   // contributes to output row oh via tap row a
                const float4 wl = wv0[3 * a + 0];
                const float4 wm = wv0[3 * a + 1];
                const float4 wr = wv0[3 * a + 2];
                acc0.x += lf   * wl.x + cc.x * wm.x + cc.y * wr.x;
                acc0.y += cc.x * wl.y + cc.y * wm.y + cc.z * wr.y;
                acc0.z += cc.y * wl.z + cc.z * wm.z + cc.w * wr.z;
                acc0.w += cc.z * wl.w + cc.w * wm.w + rt   * wr.w;
            }
            if (a > 0) {   // contributes to output row oh+1 via tap row a-1
                const float4 wl = wv1[3 * (a - 1) + 0];
                const float4 wm = wv1[3 * (a - 1) + 1];
                const float4 wr = wv1[3 * (a - 1) + 2];
                acc1.x += lf   * wl.x + cc.x * wm.x + cc.y * wr.x;
                acc1.y += cc.x * wl.y + cc.y * wm.y + cc.z * wr.y;
                acc1.z += cc.y * wl.z + cc.z * wm.z + cc.w * wr.z;
                acc1.w += cc.z * wl.w + cc.w * wm.w + rt   * wr.w;
            }
        }

        *(float4*)(op)     = acc0;
        *(float4*)(op + W) = acc1;
        op += GSTRIDE;
    }
}

extern "C" void kernel_launch(void* const* d_in, const int* in_sizes, int n_in,
                              void* d_out, int out_size)
{
    const float* x = (const float*)d_in[0];   // (8,256,64,64) f32
    const float* w = (const float*)d_in[1];   // (8,16,9,4096) f32
    float* out = (float*)d_out;               // (8,256,64,64) f32

    const int total = B * WC * (Q / 2);       // 65536 threads (2 rows each)
    agg_kernel_v7<<<total / 64, 64>>>(x, w, out);
}